// round 3
// baseline (speedup 1.0000x reference)
#include <cuda_runtime.h>
#include <cstdint>

// Problem constants
#define N_NODES 2048
#define NF4     512             // N_NODES/4 float4 columns
#define K_TOTAL 3072            // B*L
#define KC      128             // k rows per block
#define NKC     24              // k chunks (KC*NKC == K_TOTAL)
#define NBN     8               // n blocks (64 f4 cols each)
#define ROWS    3072

// Scratch device globals (no allocation allowed). Fully overwritten each launch.
__device__ float g_part[NKC * 8 * N_NODES];   // 1.5 MB partial conv sums
__device__ float g_per_node[N_NODES];         // 8 KB per-node scalars

// ---- packed f32x2 helpers (Blackwell) -------------------------------------
__device__ __forceinline__ unsigned long long pack2(float a, float b) {
    unsigned long long r;
    asm("mov.b64 %0, {%1, %2};" : "=l"(r) : "f"(a), "f"(b));
    return r;
}
__device__ __forceinline__ unsigned long long fma2(unsigned long long a,
                                                   unsigned long long b,
                                                   unsigned long long c) {
    unsigned long long d;
    asm("fma.rn.f32x2 %0, %1, %2, %3;" : "=l"(d) : "l"(a), "l"(b), "l"(c));
    return d;
}
__device__ __forceinline__ void unpack2(unsigned long long v, float& a, float& b) {
    asm("mov.b64 {%0, %1}, %2;" : "=f"(a), "=f"(b) : "l"(v));
}

// ---------------------------------------------------------------------------
// K1: partial skinny GEMM. Block = 64 f4-cols x 4 k-quarters (KC=128 rows).
// Thread (ln = tid&63, q = tid>>6) handles one f4 column over 32 k-rows with
// 8-deep float4 load batches. Quarters are reduced in SMEM; quarter 0 stores.
// grid = (8, 24) x 256 threads.
// ---------------------------------------------------------------------------
__global__ __launch_bounds__(256) void k_gemm_partial(
    const float4* __restrict__ x4, const float* __restrict__ Wc)
{
    __shared__ float sWd[KC * 8 * 2];            // 8 KB: Wc chunk, duplicated x2
    __shared__ float4 sred[3 * 64 * 8];          // 24 KB: quarters 1..3 partials

    const int tid  = threadIdx.x;
    const int ln   = tid & 63;                   // col within block
    const int q    = tid >> 6;                   // k quarter 0..3
    const int nblk = blockIdx.x;                 // 0..7
    const int kblk = blockIdx.y;                 // 0..23

    // Stage Wc rows [kblk*128, +128) duplicated into f32x2 pairs
    const float* wsrc = Wc + (size_t)kblk * KC * 8;
    #pragma unroll
    for (int i = tid; i < KC * 8 * 2; i += 256) sWd[i] = wsrc[i >> 1];
    __syncthreads();

    const int c  = nblk * 64 + ln;               // global f4 column
    const int kq = q * 32;                       // this quarter's first row (in chunk)
    const float4* xp = x4 + ((size_t)kblk * KC + kq) * NF4 + c;
    const unsigned long long* wp2 =
        reinterpret_cast<const unsigned long long*>(sWd) + (size_t)kq * 8;

    unsigned long long accp[2][8];
    #pragma unroll
    for (int p = 0; p < 2; p++)
        #pragma unroll
        for (int j = 0; j < 8; j++) accp[p][j] = 0ull;

    #pragma unroll
    for (int kk = 0; kk < 32; kk += 8) {
        float4 xv[8];
        #pragma unroll
        for (int u = 0; u < 8; u++)
            xv[u] = __ldg(xp + (size_t)(kk + u) * NF4);
        #pragma unroll
        for (int u = 0; u < 8; u++) {
            unsigned long long lo = pack2(xv[u].x, xv[u].y);
            unsigned long long hi = pack2(xv[u].z, xv[u].w);
            const unsigned long long* w = wp2 + (kk + u) * 8;
            #pragma unroll
            for (int j = 0; j < 8; j++) {
                unsigned long long wj = w[j];
                accp[0][j] = fma2(lo, wj, accp[0][j]);
                accp[1][j] = fma2(hi, wj, accp[1][j]);
            }
        }
    }

    // Quarter partials -> SMEM (quarters 1..3), quarter 0 combines + stores.
    if (q != 0) {
        float4* dst = sred + (size_t)(q - 1) * 64 * 8 + ln * 8;
        #pragma unroll
        for (int j = 0; j < 8; j++) {
            float4 o;
            unpack2(accp[0][j], o.x, o.y);
            unpack2(accp[1][j], o.z, o.w);
            dst[j] = o;
        }
    }
    __syncthreads();
    if (q == 0) {
        float4* gp4 = reinterpret_cast<float4*>(g_part);
        #pragma unroll
        for (int j = 0; j < 8; j++) {
            float4 o;
            unpack2(accp[0][j], o.x, o.y);
            unpack2(accp[1][j], o.z, o.w);
            #pragma unroll
            for (int s = 0; s < 3; s++) {
                float4 r = sred[(size_t)s * 64 * 8 + ln * 8 + j];
                o.x += r.x; o.y += r.y; o.z += r.z; o.w += r.w;
            }
            gp4[(size_t)(kblk * 8 + j) * NF4 + c] = o;
        }
    }
}

// ---------------------------------------------------------------------------
// K2: reduce 24 partials per (n,j), add bc, folded MLP, write per_node[n].
// Split-k by 2 halves (12 chunks each) combined via SMEM.
// grid = 16 x 256 (128 nodes/block).
// ---------------------------------------------------------------------------
__global__ __launch_bounds__(256) void k_reduce_mlp(
    const float* __restrict__ bc, const float* __restrict__ W1,
    const float* __restrict__ b1, const float* __restrict__ W2,
    const float* __restrict__ b2)
{
    __shared__ float sWeff[256];        // W1[0:8] + W1[8:16] folded
    __shared__ float sb1[32];
    __shared__ float sW2v[32];
    __shared__ float sred[128 * 9];

    const int tid  = threadIdx.x;
    const int half = tid >> 7;
    const int ln   = tid & 127;
    const int n    = blockIdx.x * 128 + ln;

    sWeff[tid] = W1[tid] + W1[tid + 256];
    if (tid < 32) { sb1[tid] = b1[tid]; sW2v[tid] = W2[tid]; }

    float conv[8];
    #pragma unroll
    for (int j = 0; j < 8; j++) conv[j] = 0.0f;

    const int kc0 = half * 12;
    #pragma unroll 4
    for (int kc = kc0; kc < kc0 + 12; kc++) {
        const float* p = g_part + (size_t)(kc * 8) * N_NODES + n;
        #pragma unroll
        for (int j = 0; j < 8; j++)
            conv[j] += p[(size_t)j * N_NODES];
    }

    if (half == 1) {
        #pragma unroll
        for (int j = 0; j < 8; j++) sred[ln * 9 + j] = conv[j];
    }
    __syncthreads();
    if (half == 0) {
        #pragma unroll
        for (int j = 0; j < 8; j++)
            conv[j] += sred[ln * 9 + j] + __ldg(bc + j);

        float pn = __ldg(b2);
        #pragma unroll 4
        for (int m = 0; m < 32; m++) {
            float h = sb1[m];
            #pragma unroll
            for (int j = 0; j < 8; j++)
                h = fmaf(conv[j], sWeff[j * 32 + m], h);
            h = fmaxf(h, 0.01f * h);    // leaky_relu
            pn = fmaf(h, sW2v[m], pn);
        }
        g_per_node[n] = pn;
    }
}

// ---------------------------------------------------------------------------
// K3: broadcast per_node over 3072 rows. 8 streaming 128-bit stores/thread.
// grid = 768 x 256.
// ---------------------------------------------------------------------------
__global__ __launch_bounds__(256) void k_broadcast(float4* __restrict__ out)
{
    const int c  = (blockIdx.x & 1) * 256 + threadIdx.x;  // f4 column 0..511
    const int r0 = (blockIdx.x >> 1) * 8;                 // row group of 8
    const float4 v = __ldg(reinterpret_cast<const float4*>(g_per_node) + c);
    float4* o = out + (size_t)r0 * NF4 + c;
    #pragma unroll
    for (int i = 0; i < 8; i++)
        __stcs(o + (size_t)i * NF4, v);
}

// ---------------------------------------------------------------------------
// Inputs: 0:x 1:edge_index(unused) 2:edge_attr(unused) 3:Wc 4:bc 5:W1 6:b1 7:W2 8:b2
// ---------------------------------------------------------------------------
extern "C" void kernel_launch(void* const* d_in, const int* in_sizes, int n_in,
                              void* d_out, int out_size)
{
    const float4* x4 = (const float4*)d_in[0];
    const float*  Wc = (const float*)d_in[3];
    const float*  bc = (const float*)d_in[4];
    const float*  W1 = (const float*)d_in[5];
    const float*  b1 = (const float*)d_in[6];
    const float*  W2 = (const float*)d_in[7];
    const float*  b2 = (const float*)d_in[8];
    float* out = (float*)d_out;

    k_gemm_partial<<<dim3(NBN, NKC), 256>>>(x4, Wc);
    k_reduce_mlp<<<16, 256>>>(bc, W1, b1, W2, b2);
    k_broadcast<<<768, 256>>>(reinterpret_cast<float4*>(out));
}

// round 4
// speedup vs baseline: 1.1137x; 1.1137x over previous
#include <cuda_runtime.h>
#include <cstdint>

// Problem constants
#define N_NODES 2048
#define NF4     512             // N_NODES/4 float4 columns
#define K_TOTAL 3072            // B*L
#define KC      128             // k rows per block
#define NKC     24              // k chunks (KC*NKC == K_TOTAL)
#define NBN     8               // n blocks (64 f4 cols each)
#define ROWS    3072

// Scratch device globals (no allocation allowed). Fully overwritten each launch.
__device__ float g_part[NKC * 8 * N_NODES];   // 1.5 MB partial conv sums
__device__ float g_per_node[N_NODES];         // 8 KB per-node scalars

// ---- forced-order load/fma helpers ----------------------------------------
// volatile keeps program order among ALL volatile asm: 8 loads issue
// back-to-back before any consuming fma -> guaranteed per-warp MLP=8.
__device__ __forceinline__ float4 ldg4v(const float4* p) {
    float4 v;
    asm volatile("ld.global.nc.v4.f32 {%0,%1,%2,%3}, [%4];"
                 : "=f"(v.x), "=f"(v.y), "=f"(v.z), "=f"(v.w) : "l"(p));
    return v;
}
__device__ __forceinline__ float ldg1v(const float* p) {
    float v;
    asm volatile("ld.global.nc.f32 %0, [%1];" : "=f"(v) : "l"(p));
    return v;
}
__device__ __forceinline__ unsigned long long pack2(float a, float b) {
    unsigned long long r;
    asm("mov.b64 %0, {%1, %2};" : "=l"(r) : "f"(a), "f"(b));
    return r;
}
__device__ __forceinline__ void fma2v(unsigned long long& d,
                                      unsigned long long a,
                                      unsigned long long b) {
    asm volatile("fma.rn.f32x2 %0, %1, %2, %0;" : "+l"(d) : "l"(a), "l"(b));
}
__device__ __forceinline__ void unpack2(unsigned long long v, float& a, float& b) {
    asm("mov.b64 {%0, %1}, %2;" : "=f"(a), "=f"(b) : "l"(v));
}

// ---------------------------------------------------------------------------
// K1: partial skinny GEMM. Block = 64 f4-cols x 4 k-quarters (KC=128 rows).
// Thread handles one f4 column over 32 k-rows with FORCED 8-deep f4 batches.
// Quarters reduced in SMEM; quarter 0 stores. grid = (8, 24) x 256 threads.
// ---------------------------------------------------------------------------
__global__ __launch_bounds__(256, 2) void k_gemm_partial(
    const float4* __restrict__ x4, const float* __restrict__ Wc)
{
    __shared__ float sWd[KC * 8 * 2];            // 8 KB: Wc chunk duplicated x2
    __shared__ float4 sred[3 * 64 * 8];          // 24 KB: quarters 1..3 partials

    const int tid  = threadIdx.x;
    const int ln   = tid & 63;                   // col within block
    const int q    = tid >> 6;                   // k quarter 0..3
    const int nblk = blockIdx.x;                 // 0..7
    const int kblk = blockIdx.y;                 // 0..23

    const float* wsrc = Wc + (size_t)kblk * KC * 8;
    #pragma unroll
    for (int i = tid; i < KC * 8 * 2; i += 256) sWd[i] = wsrc[i >> 1];
    __syncthreads();

    const int c  = nblk * 64 + ln;               // global f4 column
    const int kq = q * 32;
    const float4* xp = x4 + ((size_t)kblk * KC + kq) * NF4 + c;
    const unsigned long long* wp2 =
        reinterpret_cast<const unsigned long long*>(sWd) + (size_t)kq * 8;

    unsigned long long accp[2][8];
    #pragma unroll
    for (int p = 0; p < 2; p++)
        #pragma unroll
        for (int j = 0; j < 8; j++) accp[p][j] = 0ull;

    #pragma unroll
    for (int kk = 0; kk < 32; kk += 8) {
        float4 xv[8];
        #pragma unroll
        for (int u = 0; u < 8; u++)                  // 8 volatile LDG.128 back-to-back
            xv[u] = ldg4v(xp + (size_t)(kk + u) * NF4);
        #pragma unroll
        for (int u = 0; u < 8; u++) {
            unsigned long long lo = pack2(xv[u].x, xv[u].y);
            unsigned long long hi = pack2(xv[u].z, xv[u].w);
            const unsigned long long* w = wp2 + (kk + u) * 8;
            #pragma unroll
            for (int j = 0; j < 8; j++) {
                unsigned long long wj = w[j];
                fma2v(accp[0][j], lo, wj);
                fma2v(accp[1][j], hi, wj);
            }
        }
    }

    if (q != 0) {
        float4* dst = sred + (size_t)(q - 1) * 64 * 8 + ln * 8;
        #pragma unroll
        for (int j = 0; j < 8; j++) {
            float4 o;
            unpack2(accp[0][j], o.x, o.y);
            unpack2(accp[1][j], o.z, o.w);
            dst[j] = o;
        }
    }
    __syncthreads();
    if (q == 0) {
        float4* gp4 = reinterpret_cast<float4*>(g_part);
        #pragma unroll
        for (int j = 0; j < 8; j++) {
            float4 o;
            unpack2(accp[0][j], o.x, o.y);
            unpack2(accp[1][j], o.z, o.w);
            #pragma unroll
            for (int s = 0; s < 3; s++) {
                float4 r = sred[(size_t)s * 64 * 8 + ln * 8 + j];
                o.x += r.x; o.y += r.y; o.z += r.z; o.w += r.w;
            }
            gp4[(size_t)(kblk * 8 + j) * NF4 + c] = o;
        }
    }
}

// ---------------------------------------------------------------------------
// K2: reduce 24 partials per (n,j), add bc, folded MLP, write per_node[n].
// grid = 32 blocks x 256 thr; block = 64 nodes x 4 k-slices (6 chunks each).
// ---------------------------------------------------------------------------
__global__ __launch_bounds__(256) void k_reduce_mlp(
    const float* __restrict__ bc, const float* __restrict__ W1,
    const float* __restrict__ b1, const float* __restrict__ W2,
    const float* __restrict__ b2)
{
    __shared__ float sWeff[256];        // W1[0:8] + W1[8:16] folded
    __shared__ float sb1[32];
    __shared__ float sW2v[32];
    __shared__ float sred[3 * 64 * 9];  // slices 1..3, padded

    const int tid = threadIdx.x;
    const int ln  = tid & 63;           // node within block
    const int q   = tid >> 6;           // k slice 0..3
    const int n   = blockIdx.x * 64 + ln;

    sWeff[tid] = W1[tid] + W1[tid + 256];
    if (tid < 32) { sb1[tid] = b1[tid]; sW2v[tid] = W2[tid]; }

    float conv[8];
    #pragma unroll
    for (int j = 0; j < 8; j++) conv[j] = 0.0f;

    const int kc0 = q * 6;
    #pragma unroll
    for (int kc = kc0; kc < kc0 + 6; kc++) {
        const float* p = g_part + (size_t)(kc * 8) * N_NODES + n;
        float v[8];
        #pragma unroll
        for (int j = 0; j < 8; j++)                 // 8 volatile loads batched
            v[j] = ldg1v(p + (size_t)j * N_NODES);
        #pragma unroll
        for (int j = 0; j < 8; j++) conv[j] += v[j];
    }

    if (q != 0) {
        #pragma unroll
        for (int j = 0; j < 8; j++)
            sred[(size_t)(q - 1) * 64 * 9 + ln * 9 + j] = conv[j];
    }
    __syncthreads();
    if (q == 0) {
        #pragma unroll
        for (int j = 0; j < 8; j++) {
            #pragma unroll
            for (int s = 0; s < 3; s++)
                conv[j] += sred[(size_t)s * 64 * 9 + ln * 9 + j];
            conv[j] += __ldg(bc + j);
        }

        float pn = __ldg(b2);
        #pragma unroll 4
        for (int m = 0; m < 32; m++) {
            float h = sb1[m];
            #pragma unroll
            for (int j = 0; j < 8; j++)
                h = fmaf(conv[j], sWeff[j * 32 + m], h);
            h = fmaxf(h, 0.01f * h);    // leaky_relu
            pn = fmaf(h, sW2v[m], pn);
        }
        g_per_node[n] = pn;
    }
}

// ---------------------------------------------------------------------------
// K3: broadcast per_node over 3072 rows. 8 x 128-bit stores/thread (default
// caching: completes at L2, 25MB fits). grid = 768 x 256.
// ---------------------------------------------------------------------------
__global__ __launch_bounds__(256) void k_broadcast(float4* __restrict__ out)
{
    const int c  = (blockIdx.x & 1) * 256 + threadIdx.x;  // f4 column 0..511
    const int r0 = (blockIdx.x >> 1) * 8;                 // row group of 8
    const float4 v = __ldg(reinterpret_cast<const float4*>(g_per_node) + c);
    float4* o = out + (size_t)r0 * NF4 + c;
    #pragma unroll
    for (int i = 0; i < 8; i++)
        o[(size_t)i * NF4] = v;
}

// ---------------------------------------------------------------------------
// Inputs: 0:x 1:edge_index(unused) 2:edge_attr(unused) 3:Wc 4:bc 5:W1 6:b1 7:W2 8:b2
// ---------------------------------------------------------------------------
extern "C" void kernel_launch(void* const* d_in, const int* in_sizes, int n_in,
                              void* d_out, int out_size)
{
    const float4* x4 = (const float4*)d_in[0];
    const float*  Wc = (const float*)d_in[3];
    const float*  bc = (const float*)d_in[4];
    const float*  W1 = (const float*)d_in[5];
    const float*  b1 = (const float*)d_in[6];
    const float*  W2 = (const float*)d_in[7];
    const float*  b2 = (const float*)d_in[8];
    float* out = (float*)d_out;

    k_gemm_partial<<<dim3(NBN, NKC), 256>>>(x4, Wc);
    k_reduce_mlp<<<32, 256>>>(bc, W1, b1, W2, b2);
    k_broadcast<<<768, 256>>>(reinterpret_cast<float4*>(out));
}